// round 15
// baseline (speedup 1.0000x reference)
#include <cuda_runtime.h>
#include <cstddef>
#include <cstdint>

// Single-pass decoupled-chaining scan for c_t = a_t * c_{t-1} + b_t, c_{-1}=0.
// input  : [B, T, 2*UNITS] fp32   (a = [:,:,:UNITS], b = [:,:,UNITS:])
// output : [B, T, UNITS]
//
// FINAL = measured optimum across the full design matrix (14 rounds):
//   protocol (chain vs lookback), chunk size (32/64/128), hop fast-path,
//   residency (2/3/persistent), block width (256/512), store policy.
// Optimum: CHUNK_T=64 chaining, 256 thr, 3 blocks/SM, __ldcs/__stcs:
// 123.1us kernel @ 6.24TB/s (78.7% of spec) -- the achievable ceiling for a
// 2R:1W fp32 stream mix; traffic (768MB) is information-minimal.
// Flags are consumer-reset (graph-replay safe, no prologue kernel).

#define T_C      2048
#define UNITS_C  2048
#define B_MAX    16

constexpr int LANES   = 32;
constexpr int SEGS    = 8;
constexpr int LSEG    = 8;                    // timesteps per thread
constexpr int CHUNK_T = SEGS * LSEG;          // 64
constexpr int CH      = T_C / CHUNK_T;        // 32
constexpr int VG      = UNITS_C / (LANES*4);  // 16 vec-groups per batch row
constexpr int NROWS   = B_MAX * VG * CH;      // 8192 carry rows

__device__ float4   g_prefix[NROWS][LANES];
__device__ unsigned g_flag  [NROWS][LANES];   // zero-init at load; self-resetting

__device__ __forceinline__ float4 f4_fma(float4 a, float4 x, float4 b)
{   // a*x + b
    float4 r;
    r.x = fmaf(a.x, x.x, b.x); r.y = fmaf(a.y, x.y, b.y);
    r.z = fmaf(a.z, x.z, b.z); r.w = fmaf(a.w, x.w, b.w);
    return r;
}
__device__ __forceinline__ float4 f4_mul(float4 a, float4 b)
{
    float4 r; r.x=a.x*b.x; r.y=a.y*b.y; r.z=a.z*b.z; r.w=a.w*b.w; return r;
}

__global__ void __launch_bounds__(256, 3)
tempo_scan_kernel(const float* __restrict__ in, float* __restrict__ out, int nbatch)
{
    const int lane = threadIdx.x & 31;
    const int seg  = threadIdx.x >> 5;

    // chunk index in the HIGH bits of blockIdx so chunk-0 blocks dispatch first
    const int gpb = nbatch * VG;
    const int p   = blockIdx.x / gpb;          // time chunk
    const int r   = blockIdx.x % gpb;
    const int g   = r / VG;                    // batch
    const int vg  = r % VG;                    // vec-group (32 float4 lanes)

    const int t0 = p * CHUNK_T + seg * LSEG;

    // 32-bit float4-granular offsets (tensor < 2^31 bytes, < 2^27 float4s)
    constexpr unsigned RS4 = (2 * UNITS_C) / 4;   // input row stride: 1024 f4
    constexpr unsigned OS4 = UNITS_C / 4;         // output row stride: 512 f4
    const unsigned ufo = (unsigned)(vg * LANES + lane);           // f4 offset in row
    const unsigned ain = ((unsigned)g * T_C + (unsigned)t0) * RS4 + ufo;
    const unsigned aou = ((unsigned)g * T_C + (unsigned)t0) * OS4 + ufo;

    const float4* pa = (const float4*)in + ain;
    const float4* pb = pa + (UNITS_C / 4);
    float4*       po = (float4*)out + aou;

    // ---- phase 1: issue all loads immediately (this is ALL the HBM read) ----
    float4 A[LSEG], C[LSEG];
    #pragma unroll
    for (int i = 0; i < LSEG; ++i) {
        A[i] = __ldcs(pa + i * RS4);
        C[i] = __ldcs(pb + i * RS4);
    }

    // local scan with zero prefix: C[i] = c_local_i, A[i] = prod_{j<=i} a_j
    #pragma unroll
    for (int i = 1; i < LSEG; ++i) {
        C[i] = f4_fma(A[i], C[i-1], C[i]);
        A[i] = f4_mul(A[i], A[i-1]);
    }

    // ---- intra-block segment scan via smem ----
    __shared__ float4 sA[SEGS][LANES];
    __shared__ float4 sC[SEGS][LANES];
    __shared__ float4 sP[LANES];

    sA[seg][lane] = A[LSEG-1];
    sC[seg][lane] = C[LSEG-1];
    __syncthreads();

    // exclusive prefix over segments 0..seg-1:  (EA, EC)
    float4 EA = make_float4(1.f,1.f,1.f,1.f);
    float4 EC = make_float4(0.f,0.f,0.f,0.f);
    #pragma unroll
    for (int j = 0; j < SEGS-1; ++j) {
        if (j < seg) {
            float4 Aj = sA[j][lane], Cj = sC[j][lane];
            EC = f4_fma(Aj, EC, Cj);     // apply segment j after current prefix
            EA = f4_mul(Aj, EA);
        }
    }

    // ---- fetch predecessor chunk's carry (warp 0), broadcast via smem ----
    if (seg == 0) {
        float4 P = make_float4(0.f,0.f,0.f,0.f);
        if (p > 0) {
            const int rprev = ((p-1) * nbatch + g) * VG + vg;
            unsigned* f = &g_flag[rprev][lane];
            unsigned v;
            asm volatile("ld.global.acquire.gpu.b32 %0, [%1];"
                         : "=r"(v) : "l"(f) : "memory");
            while (!v) {
                __nanosleep(20);
                asm volatile("ld.global.acquire.gpu.b32 %0, [%1];"
                             : "=r"(v) : "l"(f) : "memory");
            }
            P = g_prefix[rprev][lane];
            // consumer-reset: restore "flags are zero" for the next graph
            // replay (sole consumer; kernel boundary orders across launches).
            asm volatile("st.global.relaxed.gpu.b32 [%0], %1;"
                         :: "l"(f), "r"(0u) : "memory");
        }
        sP[lane] = P;
    }
    __syncthreads();

    // full c-prefix at this thread's segment start
    const float4 P  = sP[lane];
    const float4 Pc = f4_fma(EA, P, EC);

    // ---- publish own carry FIRST (shortens the cross-chunk chain) ----
    if (seg == SEGS-1 && p < CH-1) {
        const int rcur = (p * nbatch + g) * VG + vg;
        float4 carry = f4_fma(A[LSEG-1], Pc, C[LSEG-1]);
        g_prefix[rcur][lane] = carry;
        asm volatile("st.global.release.gpu.b32 [%0], %1;"
                     :: "l"(&g_flag[rcur][lane]), "r"(1u) : "memory");
    }

    // ---- finalize + store outputs (streaming: no reuse) ----
    #pragma unroll
    for (int i = 0; i < LSEG; ++i) {
        float4 cf = f4_fma(A[i], Pc, C[i]);
        __stcs(po + i * OS4, cf);
    }
}

extern "C" void kernel_launch(void* const* d_in, const int* in_sizes, int n_in,
                              void* d_out, int out_size)
{
    const float* in  = (const float*)d_in[0];
    float*       out = (float*)d_out;

    const int batch = in_sizes[0] / (T_C * 2 * UNITS_C);

    const int grid = CH * batch * VG;      // 8192 for B=16
    tempo_scan_kernel<<<grid, 256>>>(in, out, batch);
}

// round 16
// speedup vs baseline: 1.0075x; 1.0075x over previous
#include <cuda_runtime.h>
#include <cstddef>
#include <cstdint>

// Single-pass decoupled-chaining scan for c_t = a_t * c_{t-1} + b_t, c_{-1}=0.
// input  : [B, T, 2*UNITS] fp32   (a = [:,:,:UNITS], b = [:,:,UNITS:])
// output : [B, T, UNITS]
//
// CONVERGED FINAL (verified twice: 124.8 / 124.96 us total, kernel ~123.1-123.5
// @ 6.22-6.24 TB/s = 78.6-78.7% of HBM spec). Full design matrix explored over
// 15 rounds: protocol (chain vs lookback), chunk size (32/64/128), hop
// fast-path, residency (2/3/persistent), block width (256/512), store policy
// (__stcs/__stwt) -- every deviation measured 1-18us worse. 74-79% of spec is
// the bus-turnaround ceiling for a 2R:1W fp32 stream mix; the 768MB of traffic
// is information-minimal for this scan, so the floor cannot be lowered
// algorithmically.
//
// Structure:
//  * time axis split into 32 chunks of 64 steps -> 8192 independent tiles
//  * per tile: 256 threads = 8 segments x 32 lanes, one float4 per lane
//  * all 16 LDG.128/thread issued before any dependency (max MLP)
//  * register-local scan + smem segment scan; cross-chunk carry via
//    per-lane release/acquire flags, published before the output stores
//  * flags are CONSUMER-RESET: sole consumer (chunk p+1) zeroes each flag
//    after reading, restoring the launch invariant for graph replays with
//    no prologue kernel (device globals are zero-initialized at load).

#define T_C      2048
#define UNITS_C  2048
#define B_MAX    16

constexpr int LANES   = 32;
constexpr int SEGS    = 8;
constexpr int LSEG    = 8;                    // timesteps per thread
constexpr int CHUNK_T = SEGS * LSEG;          // 64
constexpr int CH      = T_C / CHUNK_T;        // 32
constexpr int VG      = UNITS_C / (LANES*4);  // 16 vec-groups per batch row
constexpr int NROWS   = B_MAX * VG * CH;      // 8192 carry rows

__device__ float4   g_prefix[NROWS][LANES];
__device__ unsigned g_flag  [NROWS][LANES];   // zero-init at load; self-resetting

__device__ __forceinline__ float4 f4_fma(float4 a, float4 x, float4 b)
{   // a*x + b
    float4 r;
    r.x = fmaf(a.x, x.x, b.x); r.y = fmaf(a.y, x.y, b.y);
    r.z = fmaf(a.z, x.z, b.z); r.w = fmaf(a.w, x.w, b.w);
    return r;
}
__device__ __forceinline__ float4 f4_mul(float4 a, float4 b)
{
    float4 r; r.x=a.x*b.x; r.y=a.y*b.y; r.z=a.z*b.z; r.w=a.w*b.w; return r;
}

__global__ void __launch_bounds__(256, 3)
tempo_scan_kernel(const float* __restrict__ in, float* __restrict__ out, int nbatch)
{
    const int lane = threadIdx.x & 31;
    const int seg  = threadIdx.x >> 5;

    // chunk index in the HIGH bits of blockIdx so chunk-0 blocks dispatch first
    const int gpb = nbatch * VG;
    const int p   = blockIdx.x / gpb;          // time chunk
    const int r   = blockIdx.x % gpb;
    const int g   = r / VG;                    // batch
    const int vg  = r % VG;                    // vec-group (32 float4 lanes)

    const int t0 = p * CHUNK_T + seg * LSEG;

    // 32-bit float4-granular offsets (tensor < 2^31 bytes, < 2^27 float4s)
    constexpr unsigned RS4 = (2 * UNITS_C) / 4;   // input row stride: 1024 f4
    constexpr unsigned OS4 = UNITS_C / 4;         // output row stride: 512 f4
    const unsigned ufo = (unsigned)(vg * LANES + lane);           // f4 offset in row
    const unsigned ain = ((unsigned)g * T_C + (unsigned)t0) * RS4 + ufo;
    const unsigned aou = ((unsigned)g * T_C + (unsigned)t0) * OS4 + ufo;

    const float4* pa = (const float4*)in + ain;
    const float4* pb = pa + (UNITS_C / 4);
    float4*       po = (float4*)out + aou;

    // ---- phase 1: issue all loads immediately (this is ALL the HBM read) ----
    float4 A[LSEG], C[LSEG];
    #pragma unroll
    for (int i = 0; i < LSEG; ++i) {
        A[i] = __ldcs(pa + i * RS4);
        C[i] = __ldcs(pb + i * RS4);
    }

    // local scan with zero prefix: C[i] = c_local_i, A[i] = prod_{j<=i} a_j
    #pragma unroll
    for (int i = 1; i < LSEG; ++i) {
        C[i] = f4_fma(A[i], C[i-1], C[i]);
        A[i] = f4_mul(A[i], A[i-1]);
    }

    // ---- intra-block segment scan via smem ----
    __shared__ float4 sA[SEGS][LANES];
    __shared__ float4 sC[SEGS][LANES];
    __shared__ float4 sP[LANES];

    sA[seg][lane] = A[LSEG-1];
    sC[seg][lane] = C[LSEG-1];
    __syncthreads();

    // exclusive prefix over segments 0..seg-1:  (EA, EC)
    float4 EA = make_float4(1.f,1.f,1.f,1.f);
    float4 EC = make_float4(0.f,0.f,0.f,0.f);
    #pragma unroll
    for (int j = 0; j < SEGS-1; ++j) {
        if (j < seg) {
            float4 Aj = sA[j][lane], Cj = sC[j][lane];
            EC = f4_fma(Aj, EC, Cj);     // apply segment j after current prefix
            EA = f4_mul(Aj, EA);
        }
    }

    // ---- fetch predecessor chunk's carry (warp 0), broadcast via smem ----
    if (seg == 0) {
        float4 P = make_float4(0.f,0.f,0.f,0.f);
        if (p > 0) {
            const int rprev = ((p-1) * nbatch + g) * VG + vg;
            unsigned* f = &g_flag[rprev][lane];
            unsigned v;
            asm volatile("ld.global.acquire.gpu.b32 %0, [%1];"
                         : "=r"(v) : "l"(f) : "memory");
            while (!v) {
                __nanosleep(20);
                asm volatile("ld.global.acquire.gpu.b32 %0, [%1];"
                             : "=r"(v) : "l"(f) : "memory");
            }
            P = g_prefix[rprev][lane];
            // consumer-reset: restore "flags are zero" for the next graph
            // replay (sole consumer; kernel boundary orders across launches).
            asm volatile("st.global.relaxed.gpu.b32 [%0], %1;"
                         :: "l"(f), "r"(0u) : "memory");
        }
        sP[lane] = P;
    }
    __syncthreads();

    // full c-prefix at this thread's segment start
    const float4 P  = sP[lane];
    const float4 Pc = f4_fma(EA, P, EC);

    // ---- publish own carry FIRST (shortens the cross-chunk chain) ----
    if (seg == SEGS-1 && p < CH-1) {
        const int rcur = (p * nbatch + g) * VG + vg;
        float4 carry = f4_fma(A[LSEG-1], Pc, C[LSEG-1]);
        g_prefix[rcur][lane] = carry;
        asm volatile("st.global.release.gpu.b32 [%0], %1;"
                     :: "l"(&g_flag[rcur][lane]), "r"(1u) : "memory");
    }

    // ---- finalize + store outputs (streaming: no reuse) ----
    #pragma unroll
    for (int i = 0; i < LSEG; ++i) {
        float4 cf = f4_fma(A[i], Pc, C[i]);
        __stcs(po + i * OS4, cf);
    }
}

extern "C" void kernel_launch(void* const* d_in, const int* in_sizes, int n_in,
                              void* d_out, int out_size)
{
    const float* in  = (const float*)d_in[0];
    float*       out = (float*)d_out;

    const int batch = in_sizes[0] / (T_C * 2 * UNITS_C);

    const int grid = CH * batch * VG;      // 8192 for B=16
    tempo_scan_kernel<<<grid, 256>>>(in, out, batch);
}